// round 4
// baseline (speedup 1.0000x reference)
#include <cuda_runtime.h>
#include <cuda_bf16.h>
#include <cstdint>
#include <cstddef>

// ---------------------------------------------------------------------------
// Problem constants (fixed by the reference):
//   B=8, N=2048, D=1024.  scale = 1/sqrt(D_HEAD=64) = 0.125
// Pipeline:
//   Q = query @ Wq^T + bq          (NT GEMM, M=16384,N=1024,K=1024)
//   K = key   @ Wk^T + bk
//   V = value @ Wv^T + bv
//   S = (Q @ K^T + score_matrix) * 0.125   (batched NT GEMM, fused epilogue)
//   P = softmax_rows(S)
//   O = P @ V                       (batched NN GEMM)
//   out = O @ Wo^T + bo             (NT GEMM)
// ---------------------------------------------------------------------------

#define AB_B 8
#define AB_N 2048
#define AB_D 1024

// Device-global scratch (allocation-free rule: __device__ arrays are allowed).
__device__ float g_Q[(size_t)AB_B * AB_N * AB_D];
__device__ float g_K[(size_t)AB_B * AB_N * AB_D];
__device__ float g_V[(size_t)AB_B * AB_N * AB_D];
__device__ float g_S[(size_t)AB_B * AB_N * AB_N];
__device__ float g_O[(size_t)AB_B * AB_N * AB_D];

// ---------------------------------------------------------------------------
// Packed f32x2 helpers (Blackwell: fma.rn.f32x2 doubles fp32 FMA throughput).
// ---------------------------------------------------------------------------
__device__ __forceinline__ unsigned long long pk2(float x, float y) {
    unsigned long long r;
    asm("mov.b64 %0, {%1, %2};"
        : "=l"(r) : "r"(__float_as_uint(x)), "r"(__float_as_uint(y)));
    return r;
}
__device__ __forceinline__ void upk2(unsigned long long v, float& x, float& y) {
    unsigned int a, b;
    asm("mov.b64 {%0, %1}, %2;" : "=r"(a), "=r"(b) : "l"(v));
    x = __uint_as_float(a);
    y = __uint_as_float(b);
}
__device__ __forceinline__ unsigned long long ffma2(unsigned long long a,
                                                    unsigned long long b,
                                                    unsigned long long c) {
#if (__CUDA_ARCH__ >= 1000)
    unsigned long long d;
    asm("fma.rn.f32x2 %0, %1, %2, %3;" : "=l"(d) : "l"(a), "l"(b), "l"(c));
    return d;
#else
    float ax, ay, bx, by, cx, cy;
    upk2(a, ax, ay); upk2(b, bx, by); upk2(c, cx, cy);
    return pk2(fmaf(ax, bx, cx), fmaf(ay, by, cy));
#endif
}

// ---------------------------------------------------------------------------
// Tiled fp32 GEMM. BT=true: C[m,n] = sum_k A[m,k] * B[n,k]  (B row-major NxK)
//                  BT=false: C[m,n] = sum_k A[m,k] * B[k,n]  (B row-major KxN)
// EPI: 0 = none, 1 = +bias[n], 2 = (acc + E[m,n]) * scale
// Requirements: M%128==0, N%128==0, K%16==0 (true for every call here).
// ---------------------------------------------------------------------------
constexpr int BM = 128, BN = 128, BK = 16;

template <bool BT, int EPI>
__global__ void __launch_bounds__(256, 1)
gemm_f32(const float* __restrict__ A, const float* __restrict__ Bm,
         const float* __restrict__ E, float* __restrict__ C,
         int M, int N, int K,
         size_t sA, size_t sB, size_t sC, size_t sE, float scale) {
    __shared__ float As[2][BK][BM];
    __shared__ float Bs[2][BK][BN];

    const int bz = blockIdx.z;
    A += sA * (size_t)bz;
    Bm += sB * (size_t)bz;
    C += sC * (size_t)bz;
    if (EPI == 2) E += sE * (size_t)bz;

    const int bm = blockIdx.y * BM;
    const int bn = blockIdx.x * BN;
    const int tid = (int)threadIdx.x;
    const int tx = tid & 15;   // 16 cols of threads -> 8 output cols each
    const int ty = tid >> 4;   // 16 rows of threads -> 8 output rows each

    float4 aReg[2], bReg[2];
    const int nT = K / BK;

    auto fetch = [&](int t) {
        const int k0 = t * BK;
#pragma unroll
        for (int i = 0; i < 2; ++i) {
            const int v = tid + i * 256;
            const int r = v >> 2, kv = (v & 3) << 2;
            aReg[i] = *reinterpret_cast<const float4*>(
                &A[(size_t)(bm + r) * K + (k0 + kv)]);
            if (BT) {
                bReg[i] = *reinterpret_cast<const float4*>(
                    &Bm[(size_t)(bn + r) * K + (k0 + kv)]);
            } else {
                const int rb = v >> 5, cb = (v & 31) << 2;
                bReg[i] = *reinterpret_cast<const float4*>(
                    &Bm[(size_t)(k0 + rb) * N + (bn + cb)]);
            }
        }
    };
    auto stos = [&](int buf) {
#pragma unroll
        for (int i = 0; i < 2; ++i) {
            const int v = tid + i * 256;
            const int r = v >> 2, kv = (v & 3) << 2;
            As[buf][kv + 0][r] = aReg[i].x;
            As[buf][kv + 1][r] = aReg[i].y;
            As[buf][kv + 2][r] = aReg[i].z;
            As[buf][kv + 3][r] = aReg[i].w;
            if (BT) {
                Bs[buf][kv + 0][r] = bReg[i].x;
                Bs[buf][kv + 1][r] = bReg[i].y;
                Bs[buf][kv + 2][r] = bReg[i].z;
                Bs[buf][kv + 3][r] = bReg[i].w;
            } else {
                const int rb = v >> 5, cb = (v & 31) << 2;
                *reinterpret_cast<float4*>(&Bs[buf][rb][cb]) = bReg[i];
            }
        }
    };

    unsigned long long acc[8][4];
#pragma unroll
    for (int i = 0; i < 8; ++i)
#pragma unroll
        for (int j = 0; j < 4; ++j) acc[i][j] = 0ull;

    fetch(0);
    stos(0);
    __syncthreads();
    int cur = 0;
    for (int t = 0; t < nT; ++t) {
        if (t + 1 < nT) fetch(t + 1);
#pragma unroll
        for (int kk = 0; kk < BK; ++kk) {
            const float4 a0 = *reinterpret_cast<const float4*>(&As[cur][kk][ty * 8]);
            const float4 a1 = *reinterpret_cast<const float4*>(&As[cur][kk][ty * 8 + 4]);
            const float4 b0 = *reinterpret_cast<const float4*>(&Bs[cur][kk][tx * 8]);
            const float4 b1 = *reinterpret_cast<const float4*>(&Bs[cur][kk][tx * 8 + 4]);
            const unsigned long long bp[4] = {pk2(b0.x, b0.y), pk2(b0.z, b0.w),
                                              pk2(b1.x, b1.y), pk2(b1.z, b1.w)};
            const float av[8] = {a0.x, a0.y, a0.z, a0.w, a1.x, a1.y, a1.z, a1.w};
#pragma unroll
            for (int i = 0; i < 8; ++i) {
                const unsigned long long ap = pk2(av[i], av[i]);
#pragma unroll
                for (int j = 0; j < 4; ++j) acc[i][j] = ffma2(ap, bp[j], acc[i][j]);
            }
        }
        if (t + 1 < nT) {
            stos(cur ^ 1);
            __syncthreads();
        }
        cur ^= 1;
    }

    const int m0 = bm + ty * 8;
    const int n0 = bn + tx * 8;
#pragma unroll
    for (int i = 0; i < 8; ++i) {
        float out[8];
#pragma unroll
        for (int j = 0; j < 4; ++j) upk2(acc[i][j], out[2 * j], out[2 * j + 1]);
        if (EPI == 1) {
#pragma unroll
            for (int j = 0; j < 8; ++j) out[j] += E[n0 + j];
        } else if (EPI == 2) {
            const float* erow = &E[(size_t)(m0 + i) * N + n0];
#pragma unroll
            for (int j = 0; j < 8; ++j) out[j] = (out[j] + erow[j]) * scale;
        }
        float4* crow = reinterpret_cast<float4*>(&C[(size_t)(m0 + i) * N + n0]);
        crow[0] = make_float4(out[0], out[1], out[2], out[3]);
        crow[1] = make_float4(out[4], out[5], out[6], out[7]);
    }
}

// ---------------------------------------------------------------------------
// Row softmax: one 256-thread block per row of length 2048 (8 elems/thread).
// ---------------------------------------------------------------------------
__global__ void __launch_bounds__(256)
softmax_rows(float* __restrict__ S, int L) {
    __shared__ float red[8];
    float* row = S + (size_t)blockIdx.x * L;
    const int tid = (int)threadIdx.x;

    float x[8];
#pragma unroll
    for (int i = 0; i < 2; ++i) {
        const float4 v = reinterpret_cast<const float4*>(row)[tid + i * 256];
        x[4 * i + 0] = v.x; x[4 * i + 1] = v.y;
        x[4 * i + 2] = v.z; x[4 * i + 3] = v.w;
    }

    float m = x[0];
#pragma unroll
    for (int j = 1; j < 8; ++j) m = fmaxf(m, x[j]);
#pragma unroll
    for (int o = 16; o; o >>= 1) m = fmaxf(m, __shfl_xor_sync(0xffffffffu, m, o));
    if ((tid & 31) == 0) red[tid >> 5] = m;
    __syncthreads();
    m = red[0];
#pragma unroll
    for (int i = 1; i < 8; ++i) m = fmaxf(m, red[i]);
    __syncthreads();

    float e[8];
    float s = 0.f;
#pragma unroll
    for (int j = 0; j < 8; ++j) {
        e[j] = __expf(x[j] - m);
        s += e[j];
    }
#pragma unroll
    for (int o = 16; o; o >>= 1) s += __shfl_xor_sync(0xffffffffu, s, o);
    if ((tid & 31) == 0) red[tid >> 5] = s;
    __syncthreads();
    s = red[0];
#pragma unroll
    for (int i = 1; i < 8; ++i) s += red[i];
    const float inv = 1.0f / s;

#pragma unroll
    for (int i = 0; i < 2; ++i) {
        reinterpret_cast<float4*>(row)[tid + i * 256] =
            make_float4(e[4 * i + 0] * inv, e[4 * i + 1] * inv,
                        e[4 * i + 2] * inv, e[4 * i + 3] * inv);
    }
}

// ---------------------------------------------------------------------------
// Launch. Inputs (metadata order): query, key, value, score_matrix,
//   Wq, bq, Wk, bk, Wv, bv, Wo, bo.  Output: [B, N, D] fp32.
// ---------------------------------------------------------------------------
extern "C" void kernel_launch(void* const* d_in, const int* in_sizes, int n_in,
                              void* d_out, int out_size) {
    (void)in_sizes; (void)n_in; (void)out_size;
    const float* query = (const float*)d_in[0];
    const float* key   = (const float*)d_in[1];
    const float* value = (const float*)d_in[2];
    const float* smat  = (const float*)d_in[3];
    const float* Wq = (const float*)d_in[4];
    const float* bq = (const float*)d_in[5];
    const float* Wk = (const float*)d_in[6];
    const float* bk = (const float*)d_in[7];
    const float* Wv = (const float*)d_in[8];
    const float* bv = (const float*)d_in[9];
    const float* Wo = (const float*)d_in[10];
    const float* bo = (const float*)d_in[11];
    float* out = (float*)d_out;

    float *Q, *Kb, *V, *S, *O;
    cudaGetSymbolAddress((void**)&Q, g_Q);
    cudaGetSymbolAddress((void**)&Kb, g_K);
    cudaGetSymbolAddress((void**)&V, g_V);
    cudaGetSymbolAddress((void**)&S, g_S);
    cudaGetSymbolAddress((void**)&O, g_O);

    const int Bn = AB_B, Nn = AB_N, Dn = AB_D;
    const int M_all = Bn * Nn;                  // 16384
    const size_t strQ = (size_t)Nn * Dn;        // per-batch QKV stride
    const size_t strS = (size_t)Nn * Nn;        // per-batch scores stride

    // 1-3: input projections (NT, +bias vector)
    {
        dim3 g(Dn / BN, M_all / BM, 1);
        gemm_f32<true, 1><<<g, 256>>>(query, Wq, bq, Q, M_all, Dn, Dn, 0, 0, 0, 0, 1.f);
        gemm_f32<true, 1><<<g, 256>>>(key,   Wk, bk, Kb, M_all, Dn, Dn, 0, 0, 0, 0, 1.f);
        gemm_f32<true, 1><<<g, 256>>>(value, Wv, bv, V, M_all, Dn, Dn, 0, 0, 0, 0, 1.f);
    }

    // 4: S = (Q @ K^T + score_matrix) * 0.125   (batched NT, fused epilogue)
    {
        dim3 g(Nn / BN, Nn / BM, Bn);
        gemm_f32<true, 2><<<g, 256>>>(Q, Kb, smat, S, Nn, Nn, Dn,
                                      strQ, strQ, strS, strS, 0.125f);
    }

    // 5: row softmax in-place
    softmax_rows<<<Bn * Nn, 256>>>(S, Nn);

    // 6: O = P @ V  (batched NN)
    {
        dim3 g(Dn / BN, Nn / BM, Bn);
        gemm_f32<false, 0><<<g, 256>>>(S, V, nullptr, O, Nn, Dn, Nn,
                                       strS, strQ, strQ, 0, 1.f);
    }

    // 7: out = O @ Wo^T + bo
    {
        dim3 g(Dn / BN, M_all / BM, 1);
        gemm_f32<true, 1><<<g, 256>>>(O, Wo, bo, out, M_all, Dn, Dn, 0, 0, 0, 0, 1.f);
    }
}

// round 8
// speedup vs baseline: 2.6788x; 2.6788x over previous
#include <cuda_runtime.h>
#include <cuda_bf16.h>
#include <cstdint>
#include <cstddef>

// ===========================================================================
// Attention block via mma.sync (sm80-path HMMA, legal on compute_100) with
// bf16 3-term fp32 emulation.   B=8, N=2048, D=1024, scale=0.125
// All GEMMs are NT: C[m,n] = sum_k A[m,k]*B[n,k]; A,B pre-split bf16 hi/lo.
// V is produced transposed (Vt = Wv @ value^T) so P@V is also NT.
// Single GEMM kernel instantiation; epilogue variant is a runtime switch.
// ===========================================================================

#define AB_B 8
#define AB_N 2048
#define AB_D 1024
#define TOK (AB_B * AB_N)          // 16384

// ---------------------- device scratch (256B aligned) ----------------------
__device__ __align__(256) __nv_bfloat16 g_Xq_h[(size_t)TOK * AB_D], g_Xq_l[(size_t)TOK * AB_D];
__device__ __align__(256) __nv_bfloat16 g_Xk_h[(size_t)TOK * AB_D], g_Xk_l[(size_t)TOK * AB_D];
__device__ __align__(256) __nv_bfloat16 g_Xv_h[(size_t)TOK * AB_D], g_Xv_l[(size_t)TOK * AB_D];
__device__ __align__(256) __nv_bfloat16 g_Wq_h[(size_t)AB_D * AB_D], g_Wq_l[(size_t)AB_D * AB_D];
__device__ __align__(256) __nv_bfloat16 g_Wk_h[(size_t)AB_D * AB_D], g_Wk_l[(size_t)AB_D * AB_D];
__device__ __align__(256) __nv_bfloat16 g_Wv_h[(size_t)AB_D * AB_D], g_Wv_l[(size_t)AB_D * AB_D];
__device__ __align__(256) __nv_bfloat16 g_Wo_h[(size_t)AB_D * AB_D], g_Wo_l[(size_t)AB_D * AB_D];
__device__ __align__(256) __nv_bfloat16 g_Q_h[(size_t)TOK * AB_D],  g_Q_l[(size_t)TOK * AB_D];
__device__ __align__(256) __nv_bfloat16 g_K_h[(size_t)TOK * AB_D],  g_K_l[(size_t)TOK * AB_D];
__device__ __align__(256) __nv_bfloat16 g_Vt_h[(size_t)AB_D * TOK], g_Vt_l[(size_t)AB_D * TOK];
__device__ __align__(256) float         g_S[(size_t)AB_B * AB_N * AB_N];
__device__ __align__(256) __nv_bfloat16 g_P_h[(size_t)AB_B * AB_N * AB_N];
__device__ __align__(256) __nv_bfloat16 g_P_l[(size_t)AB_B * AB_N * AB_N];
__device__ __align__(256) __nv_bfloat16 g_O_h[(size_t)TOK * AB_D],  g_O_l[(size_t)TOK * AB_D];

// ------------------------------ PTX helpers --------------------------------
__device__ __forceinline__ uint32_t smem_u32(const void* p) {
    uint32_t a;
    asm("{ .reg .u64 t; cvta.to.shared.u64 t, %1; cvt.u32.u64 %0, t; }"
        : "=r"(a) : "l"(p));
    return a;
}
__device__ __forceinline__ void cp16(uint32_t dst, const void* src) {
    asm volatile("cp.async.cg.shared.global [%0], [%1], 16;"
                 :: "r"(dst), "l"(src) : "memory");
}
#define CP_COMMIT() asm volatile("cp.async.commit_group;" ::: "memory")
#define CP_WAIT(n)  asm volatile("cp.async.wait_group %0;" :: "n"(n) : "memory")

#define LDSM4(r0, r1, r2, r3, addr)                                          \
    asm volatile("ldmatrix.sync.aligned.m8n8.x4.shared.b16 {%0,%1,%2,%3}, [%4];" \
                 : "=r"(r0), "=r"(r1), "=r"(r2), "=r"(r3) : "r"(addr))

#define MMA16816(d, a0, a1, a2, a3, b0, b1)                                  \
    asm volatile("mma.sync.aligned.m16n8k16.row.col.f32.bf16.bf16.f32 "      \
                 "{%0,%1,%2,%3}, {%4,%5,%6,%7}, {%8,%9}, {%0,%1,%2,%3};"     \
                 : "+f"((d)[0]), "+f"((d)[1]), "+f"((d)[2]), "+f"((d)[3])    \
                 : "r"(a0), "r"(a1), "r"(a2), "r"(a3), "r"(b0), "r"(b1))

// ------------------------------ split helpers ------------------------------
__device__ __forceinline__ void split1(float v, __nv_bfloat16& h, __nv_bfloat16& l) {
    h = __float2bfloat16(v);
    l = __float2bfloat16(v - __bfloat162float(h));
}
__global__ void __launch_bounds__(256)
split_f32(const float* __restrict__ x, __nv_bfloat16* __restrict__ hi,
          __nv_bfloat16* __restrict__ lo, int n4) {
    int i = blockIdx.x * 256 + threadIdx.x;
    if (i >= n4) return;
    float4 v = reinterpret_cast<const float4*>(x)[i];
    __nv_bfloat16 h0, h1, h2, h3, l0, l1, l2, l3;
    split1(v.x, h0, l0); split1(v.y, h1, l1);
    split1(v.z, h2, l2); split1(v.w, h3, l3);
    reinterpret_cast<__nv_bfloat162*>(hi)[2 * i]     = __halves2bfloat162(h0, h1);
    reinterpret_cast<__nv_bfloat162*>(hi)[2 * i + 1] = __halves2bfloat162(h2, h3);
    reinterpret_cast<__nv_bfloat162*>(lo)[2 * i]     = __halves2bfloat162(l0, l1);
    reinterpret_cast<__nv_bfloat162*>(lo)[2 * i + 1] = __halves2bfloat162(l2, l3);
}

// ------------------------------- GEMM kernel -------------------------------
// 128x128x64 tile, 256 threads (8 warps as 2x4), warp tile 64x32.
// 3-stage cp.async pipeline. SW128 xor-swizzled K-major smem tiles.
// epi: 0 = +bias[col], split-write   1 = +bias[row], split-write (Vt)
//      2 = (acc+E)*scale, fp32       3 = split-write    4 = +bias[col], fp32
constexpr int GBM = 128, GBN = 128, GBK = 64;
constexpr int TILE_B = 128 * 128;            // bytes per bf16 tile (128 rows x 128B)
constexpr int STAGE_B = 4 * TILE_B;          // Ahi, Alo, Bhi, Blo = 64 KB
constexpr int NSTAGE = 3;
constexpr int GSMEM = NSTAGE * STAGE_B;      // 196608 bytes
constexpr int BPAD = 132;                    // bounce row stride (floats)

__global__ void __launch_bounds__(256, 1)
gemm_tc(const __nv_bfloat16* __restrict__ Ah, const __nv_bfloat16* __restrict__ Al,
        const __nv_bfloat16* __restrict__ Bh, const __nv_bfloat16* __restrict__ Bl,
        const float* __restrict__ bias, const float* __restrict__ E,
        void* __restrict__ C0, void* __restrict__ C1,
        int K, int lda, int ldb, int ldc, int ldE,
        size_t offA, size_t offB, size_t offC, size_t offE, float scale, int epi) {
    extern __shared__ __align__(1024) char smem[];
    const uint32_t sb = smem_u32(smem);
    const int tid = (int)threadIdx.x;
    const int wid = tid >> 5, l = tid & 31;
    const int wm = wid >> 2, wn = wid & 3;           // 2 x 4 warp grid
    const int bm = blockIdx.y * GBM, bn = blockIdx.x * GBN;
    const int z = blockIdx.z;
    Ah += offA * z; Al += offA * z;
    Bh += offB * z; Bl += offB * z;

    // Per-thread ldmatrix address pieces (row*128 and row&7) for the xor swizzle.
    const int lr = l & 15;                 // ldmatrix row lane
    const int ch = l >> 4;                 // chunk half (0/1)
    uint32_t aoff[4], axor[4], boff[2], bxor[2];
#pragma unroll
    for (int mi = 0; mi < 4; ++mi) {
        const int r = wm * 64 + mi * 16 + lr;
        aoff[mi] = (uint32_t)(r * 128);
        axor[mi] = (uint32_t)(r & 7);
    }
#pragma unroll
    for (int np = 0; np < 2; ++np) {
        const int r = wn * 32 + np * 16 + lr;
        boff[np] = (uint32_t)(r * 128);
        bxor[np] = (uint32_t)(r & 7);
    }

    const int nT = K / GBK;

    auto load_stage = [&](int t, int buf) {
        const int k0 = t * GBK;
        const uint32_t sbase = sb + (uint32_t)(buf * STAGE_B);
#pragma unroll
        for (int i = 0; i < 4; ++i) {
            const int v = tid + i * 256;              // 0..1023
            const int row = v >> 3, c = v & 7;        // 16B chunk in 128B row
            const uint32_t sw = (uint32_t)(row * 128 + ((c ^ (row & 7)) << 4));
            const size_t ga = (size_t)(bm + row) * lda + k0 + c * 8;
            const size_t gb = (size_t)(bn + row) * ldb + k0 + c * 8;
            cp16(sbase + 0 * TILE_B + sw, &Ah[ga]);
            cp16(sbase + 1 * TILE_B + sw, &Al[ga]);
            cp16(sbase + 2 * TILE_B + sw, &Bh[gb]);
            cp16(sbase + 3 * TILE_B + sw, &Bl[gb]);
        }
        CP_COMMIT();
    };

    float d[4][4][4];
#pragma unroll
    for (int mi = 0; mi < 4; ++mi)
#pragma unroll
        for (int nj = 0; nj < 4; ++nj)
#pragma unroll
            for (int q = 0; q < 4; ++q) d[mi][nj][q] = 0.f;

    load_stage(0, 0);
    load_stage(1, 1);

    for (int t = 0; t < nT; ++t) {
        if (t + 2 < nT) { CP_WAIT(1); } else { CP_WAIT(0); }
        __syncthreads();
        if (t + 2 < nT) load_stage(t + 2, (t + 2) % NSTAGE);

        const uint32_t sAh = sb + (uint32_t)((t % NSTAGE) * STAGE_B);
        const uint32_t sAl = sAh + TILE_B;
        const uint32_t sBh = sAh + 2 * TILE_B;
        const uint32_t sBl = sAh + 3 * TILE_B;
#pragma unroll
        for (int kk = 0; kk < 4; ++kk) {
            const uint32_t c = (uint32_t)(kk * 2 + ch);
            uint32_t ah[4][4], al[4][4], bh[2][4], bl[2][4];
#pragma unroll
            for (int mi = 0; mi < 4; ++mi) {
                const uint32_t off = aoff[mi] + ((c ^ axor[mi]) << 4);
                LDSM4(ah[mi][0], ah[mi][1], ah[mi][2], ah[mi][3], sAh + off);
                LDSM4(al[mi][0], al[mi][1], al[mi][2], al[mi][3], sAl + off);
            }
#pragma unroll
            for (int np = 0; np < 2; ++np) {
                const uint32_t off = boff[np] + ((c ^ bxor[np]) << 4);
                LDSM4(bh[np][0], bh[np][1], bh[np][2], bh[np][3], sBh + off);
                LDSM4(bl[np][0], bl[np][1], bl[np][2], bl[np][3], sBl + off);
            }
#pragma unroll
            for (int mi = 0; mi < 4; ++mi) {
#pragma unroll
                for (int nj = 0; nj < 4; ++nj) {
                    const int np = nj >> 1, sbi = nj & 1;
                    // hi*hi
                    MMA16816(d[mi][nj], ah[mi][0], ah[mi][1], ah[mi][2], ah[mi][3],
                             bh[np][sbi], bh[np][sbi + 2]);
                    // hi*lo
                    MMA16816(d[mi][nj], ah[mi][0], ah[mi][1], ah[mi][2], ah[mi][3],
                             bl[np][sbi], bl[np][sbi + 2]);
                    // lo*hi
                    MMA16816(d[mi][nj], al[mi][0], al[mi][1], al[mi][2], al[mi][3],
                             bh[np][sbi], bh[np][sbi + 2]);
                }
            }
        }
    }
    __syncthreads();   // all warps done with smem before bounce reuse

    // Fragment -> padded smem bounce (coalesced epilogue after).
    {
        float* bounce = reinterpret_cast<float*>(smem);
        const int fr = l >> 2, fc = (l & 3) * 2;
#pragma unroll
        for (int mi = 0; mi < 4; ++mi) {
#pragma unroll
            for (int nj = 0; nj < 4; ++nj) {
                const int r0 = wm * 64 + mi * 16 + fr;
                const int c0 = wn * 32 + (nj >> 1) * 16 + (nj & 1) * 8 + fc;
                *reinterpret_cast<float2*>(&bounce[r0 * BPAD + c0]) =
                    make_float2(d[mi][nj][0], d[mi][nj][1]);
                *reinterpret_cast<float2*>(&bounce[(r0 + 8) * BPAD + c0]) =
                    make_float2(d[mi][nj][2], d[mi][nj][3]);
            }
        }
    }
    __syncthreads();

    const float* bounce = reinterpret_cast<const float*>(smem);
#pragma unroll 4
    for (int j = 0; j < 32; ++j) {
        const int pid = tid + j * 256;        // 0..8191 float2 pairs
        const int e0 = pid * 2;
        const int row = e0 >> 7, col = e0 & 127;
        float v0 = bounce[row * BPAD + col];
        float v1 = bounce[row * BPAD + col + 1];
        const size_t gro = offC * z + (size_t)(bm + row) * ldc + (bn + col);
        if (epi == 0 || epi == 4) { v0 += bias[bn + col]; v1 += bias[bn + col + 1]; }
        else if (epi == 1) { const float bb = bias[bm + row]; v0 += bb; v1 += bb; }
        else if (epi == 2) {
            const size_t ge = offE * z + (size_t)(bm + row) * ldE + (bn + col);
            v0 = (v0 + E[ge]) * scale;
            v1 = (v1 + E[ge + 1]) * scale;
        }
        if (epi == 2 || epi == 4) {
            *reinterpret_cast<float2*>(reinterpret_cast<float*>(C0) + gro) =
                make_float2(v0, v1);
        } else {
            __nv_bfloat16 h0, h1, l0, l1;
            split1(v0, h0, l0); split1(v1, h1, l1);
            *reinterpret_cast<__nv_bfloat162*>(reinterpret_cast<__nv_bfloat16*>(C0) + gro) =
                __halves2bfloat162(h0, h1);
            *reinterpret_cast<__nv_bfloat162*>(reinterpret_cast<__nv_bfloat16*>(C1) + gro) =
                __halves2bfloat162(l0, l1);
        }
    }
}

// ------------------------------- softmax -----------------------------------
__global__ void __launch_bounds__(256)
softmax_split(const float* __restrict__ S, __nv_bfloat16* __restrict__ Ph,
              __nv_bfloat16* __restrict__ Pl) {
    __shared__ float red[8];
    const float* row = S + (size_t)blockIdx.x * AB_N;
    const int tid = (int)threadIdx.x;

    float x[8];
#pragma unroll
    for (int i = 0; i < 2; ++i) {
        const float4 v = reinterpret_cast<const float4*>(row)[tid + i * 256];
        x[4 * i + 0] = v.x; x[4 * i + 1] = v.y;
        x[4 * i + 2] = v.z; x[4 * i + 3] = v.w;
    }
    float m = x[0];
#pragma unroll
    for (int j = 1; j < 8; ++j) m = fmaxf(m, x[j]);
#pragma unroll
    for (int o = 16; o; o >>= 1) m = fmaxf(m, __shfl_xor_sync(0xffffffffu, m, o));
    if ((tid & 31) == 0) red[tid >> 5] = m;
    __syncthreads();
    m = red[0];
#pragma unroll
    for (int i = 1; i < 8; ++i) m = fmaxf(m, red[i]);
    __syncthreads();

    float e[8], s = 0.f;
#pragma unroll
    for (int j = 0; j < 8; ++j) { e[j] = __expf(x[j] - m); s += e[j]; }
#pragma unroll
    for (int o = 16; o; o >>= 1) s += __shfl_xor_sync(0xffffffffu, s, o);
    if ((tid & 31) == 0) red[tid >> 5] = s;
    __syncthreads();
    s = red[0];
#pragma unroll
    for (int i = 1; i < 8; ++i) s += red[i];
    const float inv = 1.0f / s;

    const size_t ro = (size_t)blockIdx.x * AB_N;
#pragma unroll
    for (int i = 0; i < 2; ++i) {
        const int base = (tid + i * 256) * 4;
        __nv_bfloat16 h[4], lo[4];
#pragma unroll
        for (int k = 0; k < 4; ++k) split1(e[4 * i + k] * inv, h[k], lo[k]);
        reinterpret_cast<__nv_bfloat162*>(Ph + ro + base)[0] = __halves2bfloat162(h[0], h[1]);
        reinterpret_cast<__nv_bfloat162*>(Ph + ro + base)[1] = __halves2bfloat162(h[2], h[3]);
        reinterpret_cast<__nv_bfloat162*>(Pl + ro + base)[0] = __halves2bfloat162(lo[0], lo[1]);
        reinterpret_cast<__nv_bfloat162*>(Pl + ro + base)[1] = __halves2bfloat162(lo[2], lo[3]);
    }
}

// ------------------------------- launcher ----------------------------------
static void* symaddr(const void* sym) {
    void* p = nullptr;
    cudaGetSymbolAddress(&p, sym);
    return p;
}

extern "C" void kernel_launch(void* const* d_in, const int* in_sizes, int n_in,
                              void* d_out, int out_size) {
    (void)in_sizes; (void)n_in; (void)out_size;
    const float* query = (const float*)d_in[0];
    const float* key   = (const float*)d_in[1];
    const float* value = (const float*)d_in[2];
    const float* smat  = (const float*)d_in[3];
    const float* Wq = (const float*)d_in[4];  const float* bq = (const float*)d_in[5];
    const float* Wk = (const float*)d_in[6];  const float* bk = (const float*)d_in[7];
    const float* Wv = (const float*)d_in[8];  const float* bv = (const float*)d_in[9];
    const float* Wo = (const float*)d_in[10]; const float* bo = (const float*)d_in[11];
    float* out = (float*)d_out;

    __nv_bfloat16 *Xqh = (__nv_bfloat16*)symaddr(g_Xq_h), *Xql = (__nv_bfloat16*)symaddr(g_Xq_l);
    __nv_bfloat16 *Xkh = (__nv_bfloat16*)symaddr(g_Xk_h), *Xkl = (__nv_bfloat16*)symaddr(g_Xk_l);
    __nv_bfloat16 *Xvh = (__nv_bfloat16*)symaddr(g_Xv_h), *Xvl = (__nv_bfloat16*)symaddr(g_Xv_l);
    __nv_bfloat16 *Wqh = (__nv_bfloat16*)symaddr(g_Wq_h), *Wql = (__nv_bfloat16*)symaddr(g_Wq_l);
    __nv_bfloat16 *Wkh = (__nv_bfloat16*)symaddr(g_Wk_h), *Wkl = (__nv_bfloat16*)symaddr(g_Wk_l);
    __nv_bfloat16 *Wvh = (__nv_bfloat16*)symaddr(g_Wv_h), *Wvl = (__nv_bfloat16*)symaddr(g_Wv_l);
    __nv_bfloat16 *Woh = (__nv_bfloat16*)symaddr(g_Wo_h), *Wol = (__nv_bfloat16*)symaddr(g_Wo_l);
    __nv_bfloat16 *Qh  = (__nv_bfloat16*)symaddr(g_Q_h),  *Ql  = (__nv_bfloat16*)symaddr(g_Q_l);
    __nv_bfloat16 *Kh  = (__nv_bfloat16*)symaddr(g_K_h),  *Kl  = (__nv_bfloat16*)symaddr(g_K_l);
    __nv_bfloat16 *Vth = (__nv_bfloat16*)symaddr(g_Vt_h), *Vtl = (__nv_bfloat16*)symaddr(g_Vt_l);
    float* S = (float*)symaddr(g_S);
    __nv_bfloat16 *Ph = (__nv_bfloat16*)symaddr(g_P_h), *Pl = (__nv_bfloat16*)symaddr(g_P_l);
    __nv_bfloat16 *Oh = (__nv_bfloat16*)symaddr(g_O_h), *Ol = (__nv_bfloat16*)symaddr(g_O_l);

    cudaFuncSetAttribute(gemm_tc, cudaFuncAttributeMaxDynamicSharedMemorySize, GSMEM);

    // --- 1. split fp32 inputs into bf16 hi/lo ---
    const int n4_big = TOK * AB_D / 4;
    const int n4_w   = AB_D * AB_D / 4;
    split_f32<<<n4_big / 256, 256>>>(query, Xqh, Xql, n4_big);
    split_f32<<<n4_big / 256, 256>>>(key,   Xkh, Xkl, n4_big);
    split_f32<<<n4_big / 256, 256>>>(value, Xvh, Xvl, n4_big);
    split_f32<<<n4_w / 256, 256>>>(Wq, Wqh, Wql, n4_w);
    split_f32<<<n4_w / 256, 256>>>(Wk, Wkh, Wkl, n4_w);
    split_f32<<<n4_w / 256, 256>>>(Wv, Wvh, Wvl, n4_w);
    split_f32<<<n4_w / 256, 256>>>(Wo, Woh, Wol, n4_w);

    const size_t zQ = (size_t)AB_N * AB_D;
    const size_t zS = (size_t)AB_N * AB_N;

    // --- 2. projections ---
    gemm_tc<<<dim3(AB_D / GBN, TOK / GBM, 1), 256, GSMEM>>>(
        Xqh, Xql, Wqh, Wql, bq, nullptr, Qh, Ql,
        AB_D, AB_D, AB_D, AB_D, 0, 0, 0, 0, 0, 0.f, 0);
    gemm_tc<<<dim3(AB_D / GBN, TOK / GBM, 1), 256, GSMEM>>>(
        Xkh, Xkl, Wkh, Wkl, bk, nullptr, Kh, Kl,
        AB_D, AB_D, AB_D, AB_D, 0, 0, 0, 0, 0, 0.f, 0);
    // Vt[d, tok] = sum_e Wv[d,e]*value[tok,e] + bv[d]
    gemm_tc<<<dim3(TOK / GBN, AB_D / GBM, 1), 256, GSMEM>>>(
        Wvh, Wvl, Xvh, Xvl, bv, nullptr, Vth, Vtl,
        AB_D, AB_D, AB_D, TOK, 0, 0, 0, 0, 0, 0.f, 1);

    // --- 3. scores: S = (Q K^T + smat) * 0.125 (batched) ---
    gemm_tc<<<dim3(AB_N / GBN, AB_N / GBM, AB_B), 256, GSMEM>>>(
        Qh, Ql, Kh, Kl, nullptr, smat, S, nullptr,
        AB_D, AB_D, AB_D, AB_N, AB_N, zQ, zQ, zS, zS, 0.125f, 2);

    // --- 4. softmax (writes split P) ---
    softmax_split<<<AB_B * AB_N, 256>>>(S, Ph, Pl);

    // --- 5. O = P @ V (NT vs Vt; batch advances Vt columns by 2048) ---
    gemm_tc<<<dim3(AB_D / GBN, AB_N / GBM, AB_B), 256, GSMEM>>>(
        Ph, Pl, Vth, Vtl, nullptr, nullptr, Oh, Ol,
        AB_N, AB_N, TOK, AB_D, 0, zS, (size_t)AB_N, zQ, 0, 0.f, 3);

    // --- 6. out = O @ Wo^T + bo ---
    gemm_tc<<<dim3(AB_D / GBN, TOK / GBM, 1), 256, GSMEM>>>(
        Oh, Ol, Woh, Wol, bo, nullptr, out, nullptr,
        AB_D, AB_D, AB_D, AB_D, 0, 0, 0, 0, 0, 0.f, 4);
}